// round 12
// baseline (speedup 1.0000x reference)
#include <cuda_runtime.h>
#include <cuda_bf16.h>
#include <cstdint>

// LocalAttention B=8,H=8,T=8192,E=64; 128 buckets of 64; window = prev+cur bucket.
// HMMA bf16 3-pass split, streaming flash loop. Two buckets per 128-thread CTA
// (192-row K/V slab); each warp owns 32 q-rows (two m16 tiles) so every
// ldmatrix B-fragment feeds 2x MMAs. 2 CTAs/SM, <=255 regs/thread.

#define SWZ(o) ((o) ^ (((o) >> 3) & 0x70))

// smem planes: 192 rows x 128B each
#define OKH 0
#define OKL 24576
#define OVH 49152
#define OVL 73728
#define SMEM_BYTES 98304

static __device__ __forceinline__ uint32_t cvta_s(const void* p) {
    uint32_t a;
    asm("{ .reg .u64 t; cvta.to.shared.u64 t, %1; cvt.u32.u64 %0, t; }" : "=r"(a) : "l"(p));
    return a;
}
static __device__ __forceinline__ uint32_t pkbf2(float lo, float hi) {  // first arg -> low half
    uint32_t r;
    asm("cvt.rn.bf16x2.f32 %0, %1, %2;" : "=r"(r) : "f"(hi), "f"(lo));
    return r;
}

#define LDSM4(r0,r1,r2,r3,a) \
    asm volatile("ldmatrix.sync.aligned.m8n8.x4.shared.b16 {%0,%1,%2,%3}, [%4];" \
        : "=r"(r0),"=r"(r1),"=r"(r2),"=r"(r3) : "r"(a))
#define LDSM4T(r0,r1,r2,r3,a) \
    asm volatile("ldmatrix.sync.aligned.m8n8.x4.trans.shared.b16 {%0,%1,%2,%3}, [%4];" \
        : "=r"(r0),"=r"(r1),"=r"(r2),"=r"(r3) : "r"(a))
#define MMA(d,a0,a1,a2,a3,b0,b1) \
    asm volatile("mma.sync.aligned.m16n8k16.row.col.f32.bf16.bf16.f32 " \
        "{%0,%1,%2,%3},{%4,%5,%6,%7},{%8,%9},{%0,%1,%2,%3};" \
        : "+f"((d)[0]),"+f"((d)[1]),"+f"((d)[2]),"+f"((d)[3]) \
        : "r"(a0),"r"(a1),"r"(a2),"r"(a3),"r"(b0),"r"(b1))

static __device__ __forceinline__ void split2(float2 f, uint32_t& h, uint32_t& l) {
    h = pkbf2(f.x, f.y);
    l = pkbf2(f.x - __uint_as_float(h << 16), f.y - __uint_as_float(h & 0xffff0000u));
}
static __device__ __forceinline__ void wr_hilo(char* smp, uint32_t off, int oh, int ol,
                                               float4 f0, float4 f1) {
    uint32_t h0 = pkbf2(f0.x, f0.y), h1 = pkbf2(f0.z, f0.w);
    uint32_t h2 = pkbf2(f1.x, f1.y), h3 = pkbf2(f1.z, f1.w);
    uint32_t L0 = pkbf2(f0.x - __uint_as_float(h0 << 16), f0.y - __uint_as_float(h0 & 0xffff0000u));
    uint32_t L1 = pkbf2(f0.z - __uint_as_float(h1 << 16), f0.w - __uint_as_float(h1 & 0xffff0000u));
    uint32_t L2 = pkbf2(f1.x - __uint_as_float(h2 << 16), f1.y - __uint_as_float(h2 & 0xffff0000u));
    uint32_t L3 = pkbf2(f1.z - __uint_as_float(h3 << 16), f1.w - __uint_as_float(h3 & 0xffff0000u));
    *(uint4*)(smp + oh + off) = make_uint4(h0, h1, h2, h3);
    *(uint4*)(smp + ol + off) = make_uint4(L0, L1, L2, L3);
}

__global__ __launch_bounds__(128, 2)
void local_attn_hmma(const float* __restrict__ q, const float* __restrict__ k,
                     const float* __restrict__ v, float* __restrict__ out)
{
    extern __shared__ char smc[];
    const uint32_t sb = cvta_s(smc);
    const int tid = threadIdx.x, lane = tid & 31, wp = tid >> 5;
    const int pw = blockIdx.x, bh = blockIdx.y;
    const size_t base = (size_t)bh * (8192 * 64);

    const int b    = wp >> 1;              // bucket within pair
    const int half = wp & 1;               // 32-row half within bucket
    const int rloc = half * 32;            // local q row base (0 or 32)
    const int t2 = (lane & 3) * 2;
    const int r0 = rloc + (lane >> 2);     // tile rows: r0+16t, r0+16t+8
    const int nlim = half ? 8 : 6;         // causal: chunks ks < (rloc+96)/16
    const bool wok = (pw > 0) || (b > 0);

    // ---- Q fragments for both m16 tiles, hi/lo split ----
    uint32_t qh[2][4][4], ql[2][4][4];
    {
        const float* gq = q + base + (size_t)(pw * 128 + b * 64) * 64;
        #pragma unroll
        for (int t = 0; t < 2; ++t) {
            const float* p0 = gq + (r0 + 16 * t) * 64 + t2;
            const float* p1 = gq + (r0 + 16 * t + 8) * 64 + t2;
            #pragma unroll
            for (int ke = 0; ke < 4; ++ke) {
                split2(*(const float2*)(p0 + ke * 16),     qh[t][ke][0], ql[t][ke][0]);
                split2(*(const float2*)(p1 + ke * 16),     qh[t][ke][1], ql[t][ke][1]);
                split2(*(const float2*)(p0 + ke * 16 + 8), qh[t][ke][2], ql[t][ke][2]);
                split2(*(const float2*)(p1 + ke * 16 + 8), qh[t][ke][3], ql[t][ke][3]);
            }
        }
    }

    // ---- K,V slab (192 rows x 64) -> smem hi/lo, zero-pad before seq start ----
    {
        const int row0 = pw * 128 - 64;
        #pragma unroll
        for (int it = 0; it < 12; ++it) {
            int idx = tid + it * 128;            // 192*8 = 1536 chunk-units
            int j = idx >> 3, c = idx & 7, g = row0 + j;
            float4 kf0 = make_float4(0.f,0.f,0.f,0.f), kf1 = kf0, vf0 = kf0, vf1 = kf0;
            if (g >= 0) {
                const float* pk = k + base + (size_t)g * 64 + c * 8;
                const float* pv = v + base + (size_t)g * 64 + c * 8;
                kf0 = *(const float4*)pk;  kf1 = *(const float4*)(pk + 4);
                vf0 = *(const float4*)pv;  vf1 = *(const float4*)(pv + 4);
            }
            uint32_t off = SWZ((uint32_t)(j * 128 + c * 16));
            wr_hilo(smc, off, OKH, OKL, kf0, kf1);
            wr_hilo(smc, off, OVH, OVL, vf0, vf1);
        }
    }
    __syncthreads();

    // bucket b's window = slab rows [64b, 64b+128)
    const uint32_t wb = (uint32_t)(b * 8192);
    const uint32_t kbH = sb + OKH + wb, kbL = sb + OKL + wb;
    const uint32_t vbH = sb + OVH + wb, vbL = sb + OVL + wb;

    const uint32_t rk = (uint32_t)(((lane >> 4) << 3) | (lane & 7));
    const uint32_t ck = (uint32_t)(((lane >> 3) & 1) << 4);
    const uint32_t rv = (uint32_t)((((lane >> 3) & 1) << 3) | (lane & 7));
    const uint32_t cv = (uint32_t)((lane >> 4) << 4);

    float oacc[2][8][4];
    #pragma unroll
    for (int t = 0; t < 2; ++t)
        #pragma unroll
        for (int et = 0; et < 8; ++et)
            #pragma unroll
            for (int x = 0; x < 4; ++x) oacc[t][et][x] = 0.f;
    float sm0[2] = {0.f, 0.f}, sm1[2] = {0.f, 0.f};

    // ---- streaming flash loop over window chunks (16 k/v rows each) ----
    #pragma unroll
    for (int ks = 0; ks < 8; ++ks) {
        if (ks < nlim) {
            // --- S chunk for both m16 tiles, K=64 ---
            float a2[2][8];
            #pragma unroll
            for (int t = 0; t < 2; ++t)
                #pragma unroll
                for (int x = 0; x < 8; ++x) a2[t][x] = 0.f;
            #pragma unroll
            for (int ke = 0; ke < 4; ++ke) {
                uint32_t off = SWZ((uint32_t)((((ks << 4) + rk) << 7) + ke * 32 + ck));
                uint32_t bh0, bh1, bh2, bh3, bl0, bl1, bl2, bl3;
                LDSM4(bh0, bh1, bh2, bh3, kbH + off);
                LDSM4(bl0, bl1, bl2, bl3, kbL + off);
                #pragma unroll
                for (int t = 0; t < 2; ++t) {
                    MMA(a2[t],     qh[t][ke][0], qh[t][ke][1], qh[t][ke][2], qh[t][ke][3], bh0, bh1);
                    MMA(a2[t],     qh[t][ke][0], qh[t][ke][1], qh[t][ke][2], qh[t][ke][3], bl0, bl1);
                    MMA(a2[t],     ql[t][ke][0], ql[t][ke][1], ql[t][ke][2], ql[t][ke][3], bh0, bh1);
                    MMA(a2[t] + 4, qh[t][ke][0], qh[t][ke][1], qh[t][ke][2], qh[t][ke][3], bh2, bh3);
                    MMA(a2[t] + 4, qh[t][ke][0], qh[t][ke][1], qh[t][ke][2], qh[t][ke][3], bl2, bl3);
                    MMA(a2[t] + 4, ql[t][ke][0], ql[t][ke][1], ql[t][ke][2], ql[t][ke][3], bh2, bh3);
                }
            }

            // --- mask + exp (no max subtraction; |logit| << 88) ---
            float e[2][8];
            #pragma unroll
            for (int t = 0; t < 2; ++t) {
                const int ra = r0 + 16 * t, rb = ra + 8;
                #pragma unroll
                for (int st = 0; st < 2; ++st) {
                    int j0 = ks * 16 + st * 8 + t2, j1 = j0 + 1;
                    bool v00 = (j0 <= ra + 64) && (wok || j0 >= 64);
                    bool v01 = (j1 <= ra + 64) && (wok || j1 >= 64);
                    bool v10 = (j0 <= rb + 64) && (wok || j0 >= 64);
                    bool v11 = (j1 <= rb + 64) && (wok || j1 >= 64);
                    e[t][4*st+0] = v00 ? __expf(a2[t][4*st+0]) : 0.f;
                    e[t][4*st+1] = v01 ? __expf(a2[t][4*st+1]) : 0.f;
                    e[t][4*st+2] = v10 ? __expf(a2[t][4*st+2]) : 0.f;
                    e[t][4*st+3] = v11 ? __expf(a2[t][4*st+3]) : 0.f;
                    sm0[t] += e[t][4*st+0] + e[t][4*st+1];
                    sm1[t] += e[t][4*st+2] + e[t][4*st+3];
                }
            }

            // --- P fragments (hi/lo) per tile ---
            uint32_t ph[2][4], pl[2][4];
            #pragma unroll
            for (int t = 0; t < 2; ++t) {
                ph[t][0] = pkbf2(e[t][0], e[t][1]);
                ph[t][1] = pkbf2(e[t][2], e[t][3]);
                ph[t][2] = pkbf2(e[t][4], e[t][5]);
                ph[t][3] = pkbf2(e[t][6], e[t][7]);
                pl[t][0] = pkbf2(e[t][0] - __uint_as_float(ph[t][0] << 16),
                                 e[t][1] - __uint_as_float(ph[t][0] & 0xffff0000u));
                pl[t][1] = pkbf2(e[t][2] - __uint_as_float(ph[t][1] << 16),
                                 e[t][3] - __uint_as_float(ph[t][1] & 0xffff0000u));
                pl[t][2] = pkbf2(e[t][4] - __uint_as_float(ph[t][2] << 16),
                                 e[t][5] - __uint_as_float(ph[t][2] & 0xffff0000u));
                pl[t][3] = pkbf2(e[t][6] - __uint_as_float(ph[t][3] << 16),
                                 e[t][7] - __uint_as_float(ph[t][3] & 0xffff0000u));
            }

            // --- PV for this chunk: each V fragment feeds both tiles ---
            #pragma unroll
            for (int etp = 0; etp < 4; ++etp) {
                uint32_t off = SWZ((uint32_t)((((ks << 4) + rv) << 7) + (etp << 5) + cv));
                uint32_t bh0, bh1, bh2, bh3, bl0, bl1, bl2, bl3;
                LDSM4T(bh0, bh1, bh2, bh3, vbH + off);
                LDSM4T(bl0, bl1, bl2, bl3, vbL + off);
                #pragma unroll
                for (int t = 0; t < 2; ++t) {
                    MMA(oacc[t][2*etp],   ph[t][0], ph[t][1], ph[t][2], ph[t][3], bh0, bh1);
                    MMA(oacc[t][2*etp],   ph[t][0], ph[t][1], ph[t][2], ph[t][3], bl0, bl1);
                    MMA(oacc[t][2*etp],   pl[t][0], pl[t][1], pl[t][2], pl[t][3], bh0, bh1);
                    MMA(oacc[t][2*etp+1], ph[t][0], ph[t][1], ph[t][2], ph[t][3], bh2, bh3);
                    MMA(oacc[t][2*etp+1], ph[t][0], ph[t][1], ph[t][2], ph[t][3], bl2, bl3);
                    MMA(oacc[t][2*etp+1], pl[t][0], pl[t][1], pl[t][2], pl[t][3], bh2, bh3);
                }
            }
        }
    }

    // ---- reduce sums, normalize, store ----
    float* go = out + base + (size_t)(pw * 128 + b * 64) * 64;
    #pragma unroll
    for (int t = 0; t < 2; ++t) {
        float s0 = sm0[t], s1 = sm1[t];
        s0 += __shfl_xor_sync(0xffffffffu, s0, 1);
        s0 += __shfl_xor_sync(0xffffffffu, s0, 2);
        s1 += __shfl_xor_sync(0xffffffffu, s1, 1);
        s1 += __shfl_xor_sync(0xffffffffu, s1, 2);
        const float inv0 = __fdividef(1.f, s0);
        const float inv1 = __fdividef(1.f, s1);
        const int ra = r0 + 16 * t, rb = ra + 8;
        #pragma unroll
        for (int et = 0; et < 8; ++et) {
            *(float2*)(go + ra * 64 + et * 8 + t2) =
                make_float2(oacc[t][et][0] * inv0, oacc[t][et][1] * inv0);
            *(float2*)(go + rb * 64 + et * 8 + t2) =
                make_float2(oacc[t][et][2] * inv1, oacc[t][et][3] * inv1);
        }
    }
}

extern "C" void kernel_launch(void* const* d_in, const int* in_sizes, int n_in,
                              void* d_out, int out_size)
{
    const float* q = (const float*)d_in[0];
    const float* k = (const float*)d_in[1];
    const float* v = (const float*)d_in[2];
    float* o = (float*)d_out;
    cudaFuncSetAttribute(local_attn_hmma,
                         cudaFuncAttributeMaxDynamicSharedMemorySize, SMEM_BYTES);
    dim3 grid(64, 64);   // 64 bucket-pairs x 64 batch*head
    local_attn_hmma<<<grid, 128, SMEM_BYTES>>>(q, k, v, o);
}

// round 13
// speedup vs baseline: 1.0663x; 1.0663x over previous
#include <cuda_runtime.h>
#include <cuda_bf16.h>
#include <cstdint>

// LocalAttention B=8,H=8,T=8192,E=64; 128 buckets of 64; window = prev+cur bucket.
// HMMA bf16 3-pass split, streaming flash loop. Two buckets per 256-thread CTA
// (192-row shared K/V slab), 2 CTAs/SM (16 warps). Diagonal-only masking,
// fused exp->pack, scheduler-friendly (non-volatile) MMA/LDSM asm.

#define SWZ(o) ((o) ^ (((o) >> 3) & 0x70))

// smem planes: 192 rows x 128B each
#define OKH 0
#define OKL 24576
#define OVH 49152
#define OVL 73728
#define SMEM_BYTES 98304

static __device__ __forceinline__ uint32_t cvta_s(const void* p) {
    uint32_t a;
    asm("{ .reg .u64 t; cvta.to.shared.u64 t, %1; cvt.u32.u64 %0, t; }" : "=r"(a) : "l"(p));
    return a;
}
static __device__ __forceinline__ uint32_t pkbf2(float lo, float hi) {  // first arg -> low half
    uint32_t r;
    asm("cvt.rn.bf16x2.f32 %0, %1, %2;" : "=r"(r) : "f"(hi), "f"(lo));
    return r;
}

// non-volatile: outputs are used, "memory" keeps ordering vs smem stores/barriers
// while letting ptxas schedule across pure-FP chains (exp).
#define LDSM4(r0,r1,r2,r3,a) \
    asm("ldmatrix.sync.aligned.m8n8.x4.shared.b16 {%0,%1,%2,%3}, [%4];" \
        : "=r"(r0),"=r"(r1),"=r"(r2),"=r"(r3) : "r"(a) : "memory")
#define LDSM4T(r0,r1,r2,r3,a) \
    asm("ldmatrix.sync.aligned.m8n8.x4.trans.shared.b16 {%0,%1,%2,%3}, [%4];" \
        : "=r"(r0),"=r"(r1),"=r"(r2),"=r"(r3) : "r"(a) : "memory")
#define MMA(d,a0,a1,a2,a3,b0,b1) \
    asm("mma.sync.aligned.m16n8k16.row.col.f32.bf16.bf16.f32 " \
        "{%0,%1,%2,%3},{%4,%5,%6,%7},{%8,%9},{%0,%1,%2,%3};" \
        : "+f"((d)[0]),"+f"((d)[1]),"+f"((d)[2]),"+f"((d)[3]) \
        : "r"(a0),"r"(a1),"r"(a2),"r"(a3),"r"(b0),"r"(b1))

static __device__ __forceinline__ void split2(float2 f, uint32_t& h, uint32_t& l) {
    h = pkbf2(f.x, f.y);
    l = pkbf2(f.x - __uint_as_float(h << 16), f.y - __uint_as_float(h & 0xffff0000u));
}
static __device__ __forceinline__ void wr_hilo(char* smp, uint32_t off, int oh, int ol,
                                               float4 f0, float4 f1) {
    uint32_t h0 = pkbf2(f0.x, f0.y), h1 = pkbf2(f0.z, f0.w);
    uint32_t h2 = pkbf2(f1.x, f1.y), h3 = pkbf2(f1.z, f1.w);
    uint32_t L0 = pkbf2(f0.x - __uint_as_float(h0 << 16), f0.y - __uint_as_float(h0 & 0xffff0000u));
    uint32_t L1 = pkbf2(f0.z - __uint_as_float(h1 << 16), f0.w - __uint_as_float(h1 & 0xffff0000u));
    uint32_t L2 = pkbf2(f1.x - __uint_as_float(h2 << 16), f1.y - __uint_as_float(h2 & 0xffff0000u));
    uint32_t L3 = pkbf2(f1.z - __uint_as_float(h3 << 16), f1.w - __uint_as_float(h3 & 0xffff0000u));
    *(uint4*)(smp + oh + off) = make_uint4(h0, h1, h2, h3);
    *(uint4*)(smp + ol + off) = make_uint4(L0, L1, L2, L3);
}

__global__ __launch_bounds__(256, 2)
void local_attn_hmma(const float* __restrict__ q, const float* __restrict__ k,
                     const float* __restrict__ v, float* __restrict__ out)
{
    extern __shared__ char smc[];
    const uint32_t sb = cvta_s(smc);
    const int tid = threadIdx.x, lane = tid & 31, wp = tid >> 5;
    const int pw = blockIdx.x, bh = blockIdx.y;
    const size_t base = (size_t)bh * (8192 * 64);

    const int b  = wp >> 2;             // bucket within pair (0/1)
    const int wq = wp & 3;              // warp within bucket
    const int t2 = (lane & 3) * 2;
    const int lr = lane >> 2;
    const int r0 = wq * 16 + lr, r1 = r0 + 8;   // local q rows (0..63)
    const int nlim = wq + 5;            // causal: chunks ks < wq+5; ks==nlim-1 is diagonal
    const bool wok = (pw > 0) || (b > 0);

    // diagonal-chunk masks (chunk-invariant): within-chunk col offset <= lr (row r0) / lr+8 (row r1)
    const bool d00 = (t2     <= lr);    // st0: e00 ; st1: e10
    const bool d01 = (t2 + 1 <= lr);    // st0: e01 ; st1: e11

    // ---- Q fragments straight from global, hi/lo split ----
    uint32_t qh[4][4], ql[4][4];
    {
        const float* gq = q + base + (size_t)(pw * 128 + b * 64) * 64;
        const float* p0 = gq + r0 * 64 + t2;
        const float* p1 = gq + r1 * 64 + t2;
        #pragma unroll
        for (int ke = 0; ke < 4; ++ke) {
            split2(*(const float2*)(p0 + ke * 16),     qh[ke][0], ql[ke][0]);
            split2(*(const float2*)(p1 + ke * 16),     qh[ke][1], ql[ke][1]);
            split2(*(const float2*)(p0 + ke * 16 + 8), qh[ke][2], ql[ke][2]);
            split2(*(const float2*)(p1 + ke * 16 + 8), qh[ke][3], ql[ke][3]);
        }
    }

    // ---- K,V slab (192 rows x 64) -> smem hi/lo, zero-pad before seq start ----
    {
        const int row0 = pw * 128 - 64;
        #pragma unroll
        for (int it = 0; it < 6; ++it) {
            int idx = tid + it * 256;            // 192*8 = 1536 chunk-units
            int j = idx >> 3, c = idx & 7, g = row0 + j;
            float4 kf0 = make_float4(0.f,0.f,0.f,0.f), kf1 = kf0, vf0 = kf0, vf1 = kf0;
            if (g >= 0) {
                const float* pk = k + base + (size_t)g * 64 + c * 8;
                const float* pv = v + base + (size_t)g * 64 + c * 8;
                kf0 = *(const float4*)pk;  kf1 = *(const float4*)(pk + 4);
                vf0 = *(const float4*)pv;  vf1 = *(const float4*)(pv + 4);
            }
            uint32_t off = SWZ((uint32_t)(j * 128 + c * 16));
            wr_hilo(smc, off, OKH, OKL, kf0, kf1);
            wr_hilo(smc, off, OVH, OVL, vf0, vf1);
        }
    }
    __syncthreads();

    // bucket b's window = slab rows [64b, 64b+128)
    const uint32_t wb = (uint32_t)(b * 8192);
    const uint32_t kbH = sb + OKH + wb, kbL = sb + OKL + wb;
    const uint32_t vbH = sb + OVH + wb, vbL = sb + OVL + wb;

    const uint32_t rk = (uint32_t)(((lane >> 4) << 3) | (lane & 7));
    const uint32_t ck = (uint32_t)(((lane >> 3) & 1) << 4);
    const uint32_t rv = (uint32_t)((((lane >> 3) & 1) << 3) | (lane & 7));
    const uint32_t cv = (uint32_t)((lane >> 4) << 4);

    float oacc[8][4];
    #pragma unroll
    for (int et = 0; et < 8; ++et)
        #pragma unroll
        for (int x = 0; x < 4; ++x) oacc[et][x] = 0.f;
    float s0 = 0.f, s1 = 0.f;

    // ---- streaming flash loop over window chunks (16 k/v rows each) ----
    #pragma unroll
    for (int ks = 0; ks < 8; ++ks) {
        // chunks 0..3 are the previous bucket: skip entirely when padded (!wok);
        // all live chunks below the diagonal need NO per-element mask.
        if ((ks < nlim) && (wok || ks >= 4)) {
            const bool diag = (ks == nlim - 1);

            // --- S chunk: 16 q-rows x 16 cols, K=64 ---
            float a2[8];
            #pragma unroll
            for (int x = 0; x < 8; ++x) a2[x] = 0.f;
            #pragma unroll
            for (int ke = 0; ke < 4; ++ke) {
                uint32_t off = SWZ((uint32_t)((((ks << 4) + rk) << 7) + ke * 32 + ck));
                uint32_t bh0, bh1, bh2, bh3, bl0, bl1, bl2, bl3;
                LDSM4(bh0, bh1, bh2, bh3, kbH + off);
                LDSM4(bl0, bl1, bl2, bl3, kbL + off);
                MMA(a2,     qh[ke][0], qh[ke][1], qh[ke][2], qh[ke][3], bh0, bh1);
                MMA(a2,     qh[ke][0], qh[ke][1], qh[ke][2], qh[ke][3], bl0, bl1);
                MMA(a2,     ql[ke][0], ql[ke][1], ql[ke][2], ql[ke][3], bh0, bh1);
                MMA(a2 + 4, qh[ke][0], qh[ke][1], qh[ke][2], qh[ke][3], bh2, bh3);
                MMA(a2 + 4, qh[ke][0], qh[ke][1], qh[ke][2], qh[ke][3], bl2, bl3);
                MMA(a2 + 4, ql[ke][0], ql[ke][1], ql[ke][2], ql[ke][3], bh2, bh3);
            }

            // --- exp (no max subtraction; |logit| << 88) + diagonal mask + pack ---
            uint32_t ph0, ph1, ph2, ph3, pl0, pl1, pl2, pl3;
            {   // st = 0 (cols +0..7)
                float e0 = __expf(a2[0]), e1 = __expf(a2[1]);
                float e2 = __expf(a2[2]), e3 = __expf(a2[3]);
                if (diag) { e0 = d00 ? e0 : 0.f; e1 = d01 ? e1 : 0.f; }
                s0 += e0 + e1;  s1 += e2 + e3;
                ph0 = pkbf2(e0, e1); ph1 = pkbf2(e2, e3);
                pl0 = pkbf2(e0 - __uint_as_float(ph0 << 16),
                            e1 - __uint_as_float(ph0 & 0xffff0000u));
                pl1 = pkbf2(e2 - __uint_as_float(ph1 << 16),
                            e3 - __uint_as_float(ph1 & 0xffff0000u));
            }
            {   // st = 1 (cols +8..15)
                float e0 = __expf(a2[4]), e1 = __expf(a2[5]);
                float e2 = __expf(a2[6]), e3 = __expf(a2[7]);
                if (diag) { e0 = 0.f; e1 = 0.f; e2 = d00 ? e2 : 0.f; e3 = d01 ? e3 : 0.f; }
                s0 += e0 + e1;  s1 += e2 + e3;
                ph2 = pkbf2(e0, e1); ph3 = pkbf2(e2, e3);
                pl2 = pkbf2(e0 - __uint_as_float(ph2 << 16),
                            e1 - __uint_as_float(ph2 & 0xffff0000u));
                pl3 = pkbf2(e2 - __uint_as_float(ph3 << 16),
                            e3 - __uint_as_float(ph3 & 0xffff0000u));
            }

            // --- PV for this chunk ---
            #pragma unroll
            for (int etp = 0; etp < 4; ++etp) {
                uint32_t off = SWZ((uint32_t)((((ks << 4) + rv) << 7) + (etp << 5) + cv));
                uint32_t bh0, bh1, bh2, bh3, bl0, bl1, bl2, bl3;
                LDSM4T(bh0, bh1, bh2, bh3, vbH + off);
                LDSM4T(bl0, bl1, bl2, bl3, vbL + off);
                MMA(oacc[2*etp],   ph0, ph1, ph2, ph3, bh0, bh1);
                MMA(oacc[2*etp],   ph0, ph1, ph2, ph3, bl0, bl1);
                MMA(oacc[2*etp],   pl0, pl1, pl2, pl3, bh0, bh1);
                MMA(oacc[2*etp+1], ph0, ph1, ph2, ph3, bh2, bh3);
                MMA(oacc[2*etp+1], ph0, ph1, ph2, ph3, bl2, bl3);
                MMA(oacc[2*etp+1], pl0, pl1, pl2, pl3, bh2, bh3);
            }
        }
    }

    // ---- reduce sums, normalize, store ----
    s0 += __shfl_xor_sync(0xffffffffu, s0, 1);
    s0 += __shfl_xor_sync(0xffffffffu, s0, 2);
    s1 += __shfl_xor_sync(0xffffffffu, s1, 1);
    s1 += __shfl_xor_sync(0xffffffffu, s1, 2);
    const float inv0 = __fdividef(1.f, s0);
    const float inv1 = __fdividef(1.f, s1);

    float* go = out + base + (size_t)(pw * 128 + b * 64) * 64;
    #pragma unroll
    for (int et = 0; et < 8; ++et) {
        *(float2*)(go + r0 * 64 + et * 8 + t2) =
            make_float2(oacc[et][0] * inv0, oacc[et][1] * inv0);
        *(float2*)(go + r1 * 64 + et * 8 + t2) =
            make_float2(oacc[et][2] * inv1, oacc[et][3] * inv1);
    }
}

extern "C" void kernel_launch(void* const* d_in, const int* in_sizes, int n_in,
                              void* d_out, int out_size)
{
    const float* q = (const float*)d_in[0];
    const float* k = (const float*)d_in[1];
    const float* v = (const float*)d_in[2];
    float* o = (float*)d_out;
    cudaFuncSetAttribute(local_attn_hmma,
                         cudaFuncAttributeMaxDynamicSharedMemorySize, SMEM_BYTES);
    dim3 grid(64, 64);   // 64 bucket-pairs x 64 batch*head
    local_attn_hmma<<<grid, 256, SMEM_BYTES>>>(q, k, v, o);
}